// round 11
// baseline (speedup 1.0000x reference)
#include <cuda_runtime.h>

#define L     4096
#define TS    64                      // tile size
#define NT    (L / TS)                // 64 tiles
#define NBLK  (NT * (NT + 1) / 2)     // 2080 tile pairs (A <= B)
#define NTHR  256

__device__ double g_clash = 0.0;
__device__ double g_pair  = 0.0;
__device__ double g_cnt   = 0.0;
__device__ unsigned int g_done = 0;

__device__ __forceinline__ float fsqrt_approx(float x) {
    float r;
    asm("sqrt.approx.f32 %0, %1;" : "=f"(r) : "f"(x));
    return r;
}

__device__ __forceinline__ float warp_sum(float v) {
    v += __shfl_down_sync(0xffffffffu, v, 16);
    v += __shfl_down_sync(0xffffffffu, v, 8);
    v += __shfl_down_sync(0xffffffffu, v, 4);
    v += __shfl_down_sync(0xffffffffu, v, 2);
    v += __shfl_down_sync(0xffffffffu, v, 1);
    return v;
}

__global__ void __launch_bounds__(NTHR, 3)
energy_kernel(const float* __restrict__ coords,
              const float* __restrict__ cmap,
              float* __restrict__ out)
{
    __shared__ float4 sA[TS], sB[TS];            // {x,y,z,0} per residue
    __shared__ float  red[32];

    const int tid = threadIdx.x;

    // decode tile pair (A <= B) from linear block index
    int k = blockIdx.x;
    int A = (int)((129.0f - sqrtf(16641.0f - 8.0f * (float)k)) * 0.5f);
    while (64 * (A + 1) - (A + 1) * A / 2 <= k) ++A;
    while (64 * A - A * (A - 1) / 2 > k) --A;
    const int B = A + (k - (64 * A - A * (A - 1) / 2));
    const bool diag = (A == B);
    const int i0 = A * TS;
    const int j0 = B * TS;

    if (tid < TS) {
        sA[tid] = make_float4(__ldg(coords + 3 * (i0 + tid) + 0),
                              __ldg(coords + 3 * (i0 + tid) + 1),
                              __ldg(coords + 3 * (i0 + tid) + 2), 0.0f);
    } else if (tid < 2 * TS) {
        const int t = tid - TS;
        sB[t] = make_float4(__ldg(coords + 3 * (j0 + t) + 0),
                            __ldg(coords + 3 * (j0 + t) + 1),
                            __ldg(coords + 3 * (j0 + t) + 2), 0.0f);
    }

    // 4x4 sub-tile per thread
    const int ti = tid >> 4;                     // 0..15
    const int tj = tid & 15;                     // 0..15
    const int ib = i0 + ti * 4;                  // global i base
    const int jb = j0 + tj * 4;                  // global j base

    // stage both contact sub-tiles: 8 independent coalesced LDG.128
    float4 c1[4], c2[4];
#pragma unroll
    for (int r = 0; r < 4; ++r)
        c1[r] = __ldg((const float4*)(cmap + (size_t)(ib + r) * L + jb));
#pragma unroll
    for (int r = 0; r < 4; ++r)
        c2[r] = __ldg((const float4*)(cmap + (size_t)(jb + r) * L + ib));

    float aclash = 0.0f, apair = 0.0f, acnt = 0.0f;

    // ordered-entry count: c1 always; c2 only off-diag (diag would double-count)
#pragma unroll
    for (int r = 0; r < 4; ++r)
        acnt += (c1[r].x + c1[r].y) + (c1[r].z + c1[r].w);
    if (!diag)
#pragma unroll
        for (int r = 0; r < 4; ++r)
            acnt += (c2[r].x + c2[r].y) + (c2[r].z + c2[r].w);

    __syncthreads();

    float4 pj[4];
#pragma unroll
    for (int b = 0; b < 4; ++b) pj[b] = sB[tj * 4 + b];

#pragma unroll
    for (int a = 0; a < 4; ++a) {
        const float4 pi = sA[ti * 4 + a];
        const float c1v[4] = {c1[a].x, c1[a].y, c1[a].z, c1[a].w};
#pragma unroll
        for (int b = 0; b < 4; ++b) {
            float c2v = (b == 0) ? ((a == 0) ? c2[0].x : (a == 1) ? c2[0].y : (a == 2) ? c2[0].z : c2[0].w)
                      : (b == 1) ? ((a == 0) ? c2[1].x : (a == 1) ? c2[1].y : (a == 2) ? c2[1].z : c2[1].w)
                      : (b == 2) ? ((a == 0) ? c2[2].x : (a == 1) ? c2[2].y : (a == 2) ? c2[2].z : c2[2].w)
                                 : ((a == 0) ? c2[3].x : (a == 1) ? c2[3].y : (a == 2) ? c2[3].z : c2[3].w);
            float dx = pj[b].x - pi.x;
            float dy = pj[b].y - pi.y;
            float dz = pj[b].z - pi.z;
            float d2 = fmaf(dz, dz, fmaf(dy, dy, dx * dx));
            float d  = fsqrt_approx(d2);
            float t  = fmaxf(3.4f - d, 0.0f);
            float s  = c1v[b] + c2v;             // cv_ij + cv_ji
            if (diag) {
                float mask = (jb + b > ib + a) ? 1.0f : 0.0f;   // j > i only
                t *= mask;
                s *= mask;
            }
            aclash   = fmaf(t, t, aclash);
            float u  = d - 9.0f;                 // target = 6.0 * 1.5
            float w  = u * s;
            apair    = fmaf(w, u, apair);
        }
    }

    // near-band correction (diag blocks own it): remove unordered pairs with
    // j-i in {1,2}. Same expression order as the main loop -> exact cancel.
    if (diag && tid < 2 * TS) {
        const int o = 1 + (tid >> 6);
        const int i = i0 + (tid & 63);
        const int j = i + o;
        if (j < L) {
            float xi = __ldg(coords + 3 * i + 0);
            float yi = __ldg(coords + 3 * i + 1);
            float zi = __ldg(coords + 3 * i + 2);
            float xJ = __ldg(coords + 3 * j + 0);
            float yJ = __ldg(coords + 3 * j + 1);
            float zJ = __ldg(coords + 3 * j + 2);
            float dx = xJ - xi, dy = yJ - yi, dz = zJ - zi;
            float d2 = fmaf(dz, dz, fmaf(dy, dy, dx * dx));
            float d  = fsqrt_approx(d2);
            float t  = fmaxf(3.4f - d, 0.0f);
            aclash   = fmaf(-t, t, aclash);
            float s  = __ldg(cmap + (size_t)i * L + j) + __ldg(cmap + (size_t)j * L + i);
            float u  = d - 9.0f;
            float w  = u * s;
            apair    = fmaf(-w, u, apair);
        }
    }

    // block reduction
    aclash = warp_sum(aclash);
    apair  = warp_sum(apair);
    acnt   = warp_sum(acnt);
    const int wid  = tid >> 5;
    const int lane = tid & 31;
    if (lane == 0) {
        red[wid]      = aclash;
        red[8 + wid]  = apair;
        red[16 + wid] = acnt;
    }
    __syncthreads();
    if (tid == 0) {
        float cs = 0.0f, ps = 0.0f, ns = 0.0f;
        for (int w = 0; w < 8; ++w) { cs += red[w]; ps += red[8 + w]; ns += red[16 + w]; }
        atomicAdd(&g_clash, (double)cs);
        atomicAdd(&g_pair,  (double)ps);
        atomicAdd(&g_cnt,   (double)ns);
        __threadfence();
        unsigned prev = atomicAdd(&g_done, 1u);
        red[24] = (prev == (unsigned)(NBLK - 1)) ? 1.0f : 0.0f;
    }
    __syncthreads();

    // last block: bond term + finalize + reset for next graph replay
    if (red[24] != 0.0f) {
        float b = 0.0f;
        for (int k2 = tid; k2 < L - 1; k2 += NTHR) {
            float dx = __ldg(coords + 3 * k2 + 3) - __ldg(coords + 3 * k2 + 0);
            float dy = __ldg(coords + 3 * k2 + 4) - __ldg(coords + 3 * k2 + 1);
            float dz = __ldg(coords + 3 * k2 + 5) - __ldg(coords + 3 * k2 + 2);
            float d  = fsqrt_approx(fmaf(dz, dz, fmaf(dy, dy, dx * dx)));
            float t  = d - 6.0f;                 // IDEAL_C1_C1
            b = fmaf(t, t, b);
        }
        b = warp_sum(b);
        __syncthreads();
        if (lane == 0) red[wid] = b;
        __syncthreads();
        if (tid == 0) {
            float bs = 0.0f;
            for (int w = 0; w < 8; ++w) bs += red[w];
            double e_bond  = (double)bs / (double)(L - 1);
            double e_clash = g_clash / (double)L;   // unordered j>=i+3, counted once
            double cnt     = g_cnt < 1.0 ? 1.0 : g_cnt;
            double e_pair  = g_pair / cnt;
            out[0] = (float)(e_bond + 2.0 * e_clash + 0.5 * e_pair);
            g_clash = 0.0;
            g_pair  = 0.0;
            g_cnt   = 0.0;
            g_done  = 0u;
        }
    }
}

extern "C" void kernel_launch(void* const* d_in, const int* in_sizes, int n_in,
                              void* d_out, int out_size) {
    const float* a0 = (const float*)d_in[0];
    const float* a1 = (const float*)d_in[1];
    // coords is the small input (L*3), contact_map the big one (L*L)
    const float* coords = (in_sizes[0] < in_sizes[1]) ? a0 : a1;
    const float* cmap   = (in_sizes[0] < in_sizes[1]) ? a1 : a0;
    energy_kernel<<<NBLK, NTHR>>>(coords, cmap, (float*)d_out);
}

// round 12
// speedup vs baseline: 1.4848x; 1.4848x over previous
#include <cuda_runtime.h>

#define L     4096
#define TS    64                      // tile size
#define NT    (L / TS)                // 64 tiles
#define NBLK  (NT * (NT + 1) / 2)     // 2080 tile pairs (A <= B)
#define NTHR  128
#define SPAD  69                      // c2s row stride in floats

__device__ double g_clash = 0.0;
__device__ double g_pair  = 0.0;
__device__ double g_cnt   = 0.0;
__device__ unsigned int g_done = 0;

__device__ __forceinline__ float fsqrt_approx(float x) {
    float r;
    asm("sqrt.approx.f32 %0, %1;" : "=f"(r) : "f"(x));
    return r;
}

__device__ __forceinline__ float warp_sum(float v) {
    v += __shfl_down_sync(0xffffffffu, v, 16);
    v += __shfl_down_sync(0xffffffffu, v, 8);
    v += __shfl_down_sync(0xffffffffu, v, 4);
    v += __shfl_down_sync(0xffffffffu, v, 2);
    v += __shfl_down_sync(0xffffffffu, v, 1);
    return v;
}

// Sweep an 8x4 subtile. DIAG masks to j > i inside the diagonal tile.
template <bool DIAG>
__device__ __forceinline__ void sweep(
    int ib, int jb, int ti, int tj,
    const float4* __restrict__ c1, const float4* __restrict__ pj,
    const float4* sA4, const float* c2s,
    float& oclash, float& opair, float& ocnt)
{
    float cl0 = 0.0f, cl1 = 0.0f;       // split accumulator chains (b parity)
    float pa0 = 0.0f, pa1 = 0.0f;
    float cn0 = 0.0f, cn1 = 0.0f;
#pragma unroll
    for (int a = 0; a < 8; ++a) {
        const float4 pi = sA4[ti * 8 + a];          // broadcast LDS.128
        const float c1v[4] = {c1[a].x, c1[a].y, c1[a].z, c1[a].w};
#pragma unroll
        for (int b = 0; b < 4; ++b) {
            float cv2 = c2s[(tj * 4 + b) * SPAD + ti * 8 + a];
            float dx = pj[b].x - pi.x;
            float dy = pj[b].y - pi.y;
            float dz = pj[b].z - pi.z;
            float d2 = fmaf(dz, dz, fmaf(dy, dy, dx * dx));
            float d  = fsqrt_approx(d2);
            float t  = fmaxf(3.4f - d, 0.0f);
            float s  = c1v[b] + cv2;                // cv_ij + cv_ji
            if (DIAG) {
                float mask = (jb + b > ib + a) ? 1.0f : 0.0f;
                t *= mask;
                s *= mask;
            }
            float u = d - 9.0f;                     // target = 6.0 * 1.5
            float w = u * s;
            if (b & 1) { cl1 = fmaf(t, t, cl1); pa1 = fmaf(w, u, pa1); cn1 += s; }
            else       { cl0 = fmaf(t, t, cl0); pa0 = fmaf(w, u, pa0); cn0 += s; }
        }
    }
    oclash += cl0 + cl1;
    opair  += pa0 + pa1;
    ocnt   += cn0 + cn1;
}

__global__ void __launch_bounds__(NTHR, 7)
energy_kernel(const float* __restrict__ coords,
              const float* __restrict__ cmap,
              float* __restrict__ out)
{
    __shared__ float4 sA4[TS], sB4[TS];      // {x,y,z,0} per residue
    __shared__ float  c2s[TS * SPAD];        // C2 tile rows (j'), padded stride
    __shared__ float  red[16];

    const int tid = threadIdx.x;

    // decode tile pair (A <= B) from linear block index
    int k = blockIdx.x;
    int A = (int)((129.0f - sqrtf(16641.0f - 8.0f * (float)k)) * 0.5f);
    while (64 * (A + 1) - (A + 1) * A / 2 <= k) ++A;
    while (64 * A - A * (A - 1) / 2 > k) --A;
    const int B = A + (k - (64 * A - A * (A - 1) / 2));
    const bool diag = (A == B);
    const int i0 = A * TS;
    const int j0 = B * TS;

    // stage tile coords
    if (tid < TS) {
        sA4[tid] = make_float4(__ldg(coords + 3 * (i0 + tid) + 0),
                               __ldg(coords + 3 * (i0 + tid) + 1),
                               __ldg(coords + 3 * (i0 + tid) + 2), 0.0f);
    } else {
        const int t = tid - TS;
        sB4[t] = make_float4(__ldg(coords + 3 * (j0 + t) + 0),
                             __ldg(coords + 3 * (j0 + t) + 1),
                             __ldg(coords + 3 * (j0 + t) + 2), 0.0f);
    }

    // stage C2 = cmap[B-rows][A-cols]: 8 coalesced LDG.128 per thread
#pragma unroll
    for (int m = 0; m < 8; ++m) {
        const int s  = tid + m * NTHR;
        const int jr = s >> 4;                   // C2 row (j - j0)
        const int qc = s & 15;                   // i quad
        float4 v = __ldg(((const float4*)(cmap + (size_t)(j0 + jr) * L + i0)) + qc);
        float* dst = c2s + jr * SPAD + qc * 4;
        dst[0] = v.x; dst[1] = v.y; dst[2] = v.z; dst[3] = v.w;
    }

    // 8x4 subtile per thread
    const int ti = tid >> 4;                     // 0..7  -> 8 i-rows
    const int tj = tid & 15;                     // 0..15 -> 4 j-cols
    const int ib = i0 + ti * 8;
    const int jb = j0 + tj * 4;

    // prefetch C1 sub-rows: 8 independent coalesced LDG.128
    float4 c1[8];
#pragma unroll
    for (int r = 0; r < 8; ++r)
        c1[r] = __ldg(((const float4*)(cmap + (size_t)(ib + r) * L + j0)) + tj);

    __syncthreads();

    float4 pj[4];
#pragma unroll
    for (int b = 0; b < 4; ++b) pj[b] = sB4[tj * 4 + b];

    float aclash = 0.0f, apair = 0.0f, acnt = 0.0f;
    if (diag) sweep<true >(ib, jb, ti, tj, c1, pj, sA4, c2s, aclash, apair, acnt);
    else      sweep<false>(ib, jb, ti, tj, c1, pj, sA4, c2s, aclash, apair, acnt);

    // diag blocks: (1) count diagonal entries c_ii (in n_pairs, not swept);
    // (2) remove band pairs j-i in {1,2} (same fp expressions -> exact cancel)
    if (diag) {
        if (tid < TS)
            acnt += __ldg(cmap + (size_t)(i0 + tid) * L + (i0 + tid));
        const int o = 1 + (tid >> 6);            // 1 or 2
        const int i = i0 + (tid & 63);
        const int j = i + o;
        if (j < L) {
            float xi = __ldg(coords + 3 * i + 0);
            float yi = __ldg(coords + 3 * i + 1);
            float zi = __ldg(coords + 3 * i + 2);
            float xJ = __ldg(coords + 3 * j + 0);
            float yJ = __ldg(coords + 3 * j + 1);
            float zJ = __ldg(coords + 3 * j + 2);
            float dx = xJ - xi, dy = yJ - yi, dz = zJ - zi;
            float d2 = fmaf(dz, dz, fmaf(dy, dy, dx * dx));
            float d  = fsqrt_approx(d2);
            float t  = fmaxf(3.4f - d, 0.0f);
            aclash   = fmaf(-t, t, aclash);
            float s  = __ldg(cmap + (size_t)i * L + j) + __ldg(cmap + (size_t)j * L + i);
            float u  = d - 9.0f;
            float w  = u * s;
            apair    = fmaf(-w, u, apair);
            // NOTE: band contacts stay in acnt (reference counts them in n_pairs)
        }
    }

    // block reduction (4 warps)
    aclash = warp_sum(aclash);
    apair  = warp_sum(apair);
    acnt   = warp_sum(acnt);
    const int wid  = tid >> 5;
    const int lane = tid & 31;
    if (lane == 0) {
        red[wid]      = aclash;
        red[4 + wid]  = apair;
        red[8 + wid]  = acnt;
    }
    __syncthreads();
    if (tid == 0) {
        float cs = 0.0f, ps = 0.0f, ns = 0.0f;
        for (int w = 0; w < 4; ++w) { cs += red[w]; ps += red[4 + w]; ns += red[8 + w]; }
        atomicAdd(&g_clash, (double)cs);
        atomicAdd(&g_pair,  (double)ps);
        atomicAdd(&g_cnt,   (double)ns);
        __threadfence();
        unsigned prev = atomicAdd(&g_done, 1u);
        red[12] = (prev == (unsigned)(NBLK - 1)) ? 1.0f : 0.0f;
    }
    __syncthreads();

    // last block: bond term + finalize + reset for next graph replay
    if (red[12] != 0.0f) {
        float b = 0.0f;
        for (int k2 = tid; k2 < L - 1; k2 += NTHR) {
            float dx = __ldg(coords + 3 * k2 + 3) - __ldg(coords + 3 * k2 + 0);
            float dy = __ldg(coords + 3 * k2 + 4) - __ldg(coords + 3 * k2 + 1);
            float dz = __ldg(coords + 3 * k2 + 5) - __ldg(coords + 3 * k2 + 2);
            float d  = fsqrt_approx(fmaf(dz, dz, fmaf(dy, dy, dx * dx)));
            float t  = d - 6.0f;                 // IDEAL_C1_C1
            b = fmaf(t, t, b);
        }
        b = warp_sum(b);
        __syncthreads();
        if (lane == 0) red[wid] = b;
        __syncthreads();
        if (tid == 0) {
            float bs = 0.0f;
            for (int w = 0; w < 4; ++w) bs += red[w];
            double e_bond  = (double)bs / (double)(L - 1);
            double e_clash = g_clash / (double)L;   // unordered j>=i+3, counted once
            double cnt     = g_cnt < 1.0 ? 1.0 : g_cnt;
            double e_pair  = g_pair / cnt;
            out[0] = (float)(e_bond + 2.0 * e_clash + 0.5 * e_pair);
            g_clash = 0.0;
            g_pair  = 0.0;
            g_cnt   = 0.0;
            g_done  = 0u;
        }
    }
}

extern "C" void kernel_launch(void* const* d_in, const int* in_sizes, int n_in,
                              void* d_out, int out_size) {
    const float* a0 = (const float*)d_in[0];
    const float* a1 = (const float*)d_in[1];
    // coords is the small input (L*3), contact_map the big one (L*L)
    const float* coords = (in_sizes[0] < in_sizes[1]) ? a0 : a1;
    const float* cmap   = (in_sizes[0] < in_sizes[1]) ? a1 : a0;
    energy_kernel<<<NBLK, NTHR>>>(coords, cmap, (float*)d_out);
}